// round 4
// baseline (speedup 1.0000x reference)
#include <cuda_runtime.h>

// EdgeClassification: logits[e] = emb[src]@Wsrc@Wcls + emb[dst]@Wdst@Wcls + (b_fuse@Wcls + b_cls)
// Restructured: fold weight products once, project all nodes once (50K x 21 x 2 tables),
// then per-edge work is a 21-float add of two gathered rows.

#define D 128
#define NC 21
#define CP 24          // padded row: 24 floats = 96B = exactly 3 L2 sectors, 16B aligned
#define MAXN 50000
#define EPB 256        // edges per block in edge kernel

__device__ float g_Msrc[D * NC];
__device__ float g_Mdst[D * NC];
__device__ float g_bprime[NC];
__device__ float g_Psrc[MAXN * CP];
__device__ float g_Pdst[MAXN * CP];

// ---------------------------------------------------------------------------
// Kernel A: fold weights.  M_t[k][c] = sum_j Wfuse_t[k][j] * Wcls[j][c]
//           b'[c] = b_cls[c] + sum_j b_fuse[j] * Wcls[j][c]
// grid = 43 blocks x 128 threads. Blocks 0..41: (table, class) pairs. Block 42: bias.
// ---------------------------------------------------------------------------
__global__ void __launch_bounds__(128) prep_kernel(
    const float* __restrict__ Wsrc, const float* __restrict__ Wdst,
    const float* __restrict__ bfuse, const float* __restrict__ Wcls,
    const float* __restrict__ bcls)
{
    int b = blockIdx.x;
    if (b < 2 * NC) {
        int table = b / NC;
        int c = b % NC;
        const float* Wf = table ? Wdst : Wsrc;
        int k = threadIdx.x;  // 0..127
        float acc = 0.f;
        #pragma unroll 8
        for (int j = 0; j < D; ++j)
            acc += Wf[k * D + j] * Wcls[j * NC + c];
        (table ? g_Mdst : g_Msrc)[k * NC + c] = acc;
    } else {
        int c = threadIdx.x;
        if (c < NC) {
            float acc = bcls[c];
            for (int j = 0; j < D; ++j)
                acc += bfuse[j] * Wcls[j * NC + c];
            g_bprime[c] = acc;
        }
    }
}

// ---------------------------------------------------------------------------
// Kernel B: project all nodes through both folded matrices.
//   P_src[n][c] = emb[n] . Msrc[:,c] + b'[c]     (bias folded into src table)
//   P_dst[n][c] = emb[n] . Mdst[:,c]
// grid = (ceil(N/128), 2), block = 128. One thread per (node, table).
// M tile staged in smem (broadcast reads, conflict-free).
// ---------------------------------------------------------------------------
__global__ void __launch_bounds__(128) project_kernel(
    const float* __restrict__ emb, int N)
{
    __shared__ float sM[D * NC];
    __shared__ float sb[NC];
    const int table = blockIdx.y;
    {
        const float* M = table ? g_Mdst : g_Msrc;
        for (int i = threadIdx.x; i < D * NC; i += blockDim.x)
            sM[i] = M[i];
        if (threadIdx.x < NC)
            sb[threadIdx.x] = table ? 0.f : g_bprime[threadIdx.x];
    }
    __syncthreads();

    int n = blockIdx.x * blockDim.x + threadIdx.x;
    if (n >= N) return;

    float acc[NC];
    #pragma unroll
    for (int c = 0; c < NC; ++c) acc[c] = sb[c];

    const float4* ev = reinterpret_cast<const float4*>(emb + (size_t)n * D);
    #pragma unroll 2
    for (int kk = 0; kk < D / 4; ++kk) {
        float4 v = ev[kk];
        const float* m0 = &sM[(4 * kk + 0) * NC];
        const float* m1 = &sM[(4 * kk + 1) * NC];
        const float* m2 = &sM[(4 * kk + 2) * NC];
        const float* m3 = &sM[(4 * kk + 3) * NC];
        #pragma unroll
        for (int c = 0; c < NC; ++c) {
            float a = acc[c];
            a = fmaf(v.x, m0[c], a);
            a = fmaf(v.y, m1[c], a);
            a = fmaf(v.z, m2[c], a);
            a = fmaf(v.w, m3[c], a);
            acc[c] = a;
        }
    }

    float* P = (table ? g_Pdst : g_Psrc) + (size_t)n * CP;
    #pragma unroll
    for (int c = 0; c < NC; ++c) P[c] = acc[c];
}

// ---------------------------------------------------------------------------
// Kernel C: per-edge gather + add, smem-staged for fully coalesced output.
// Auto-detects edge_index element width (int64 vs int32): for int64 data
// interpreted as int32 pairs, every high word is 0 (indices < 50000).
// ---------------------------------------------------------------------------
__global__ void __launch_bounds__(EPB) edge_kernel(
    const int* __restrict__ ei32, float* __restrict__ out, int E)
{
    __shared__ float tile[EPB * NC];

    // dtype sniff: uniform across all threads/blocks (no divergence).
    // int64 => words at odd positions (high words) are all zero.
    bool is64 = ((ei32[1] | ei32[3] | ei32[5] | ei32[7]) == 0);

    const int tid = threadIdx.x;
    const long long base = (long long)blockIdx.x * EPB;
    const int valid = min((long long)EPB, (long long)E - base);

    if (tid < valid) {
        long long e = base + tid;
        long long s, d;
        if (is64) {
            const long long* ei = reinterpret_cast<const long long*>(ei32);
            s = ei[e];
            d = ei[(long long)E + e];
        } else {
            s = ei32[e];
            d = ei32[(long long)E + e];
        }
        const float4* ps = reinterpret_cast<const float4*>(g_Psrc + s * CP);
        const float4* pd = reinterpret_cast<const float4*>(g_Pdst + d * CP);
        float r[CP];
        #pragma unroll
        for (int j = 0; j < 6; ++j) {           // 6 x float4 = full 96B row (3 sectors)
            float4 a = ps[j];
            float4 b = pd[j];
            r[4 * j + 0] = a.x + b.x;
            r[4 * j + 1] = a.y + b.y;
            r[4 * j + 2] = a.z + b.z;
            r[4 * j + 3] = a.w + b.w;
        }
        // packed 21-stride smem writes: 21 coprime to 32 -> conflict-free
        #pragma unroll
        for (int c = 0; c < NC; ++c)
            tile[tid * NC + c] = r[c];
    }
    __syncthreads();

    // Coalesced copy smem -> gmem. Block output offset = blockIdx*EPB*NC*4 bytes
    // = blockIdx*21504, 16B-aligned.
    const int total = valid * NC;
    float* outp = out + base * NC;
    if ((total & 3) == 0) {
        float4* o4 = reinterpret_cast<float4*>(outp);
        const float4* t4 = reinterpret_cast<const float4*>(tile);
        const int nv = total >> 2;  // full block: 1344
        for (int i = tid; i < nv; i += EPB)
            o4[i] = t4[i];
    } else {
        for (int i = tid; i < total; i += EPB)
            outp[i] = tile[i];
    }
}

// ---------------------------------------------------------------------------
extern "C" void kernel_launch(void* const* d_in, const int* in_sizes, int n_in,
                              void* d_out, int out_size)
{
    const float* emb   = (const float*)d_in[0];
    const int*   ei    = (const int*)  d_in[1];   // width auto-detected in-kernel
    const float* Wsrc  = (const float*)d_in[2];
    const float* Wdst  = (const float*)d_in[3];
    const float* bfuse = (const float*)d_in[4];
    const float* Wcls  = (const float*)d_in[5];
    const float* bcls  = (const float*)d_in[6];
    float* out = (float*)d_out;

    int N = in_sizes[0] / D;
    if (N > MAXN) N = MAXN;
    int E = in_sizes[1] / 2;

    prep_kernel<<<2 * NC + 1, 128>>>(Wsrc, Wdst, bfuse, Wcls, bcls);

    dim3 gB((N + 127) / 128, 2);
    project_kernel<<<gB, 128>>>(emb, N);

    int gC = (E + EPB - 1) / EPB;
    edge_kernel<<<gC, EPB>>>(ei, out, E);
}